// round 11
// baseline (speedup 1.0000x reference)
#include <cuda_runtime.h>
#include <math.h>

#define BB 8
#define NN 2048
#define FF 128
#define NWRD (NN / 32)   // 64 bitmask words per row

#define K3_BLKS (BB * 129)       // 1032: A-scan + S blocks, batch-major
#define K5_BLKS (BB * 64)        // 512:  output blocks
#define ALL_BLKS (K3_BLKS + K5_BLKS)

// ---------------- scratch (device globals; no allocations allowed) ----------
__device__ float    g_c[FF];                  // c = W @ a_i
__device__ float    g_u[BB * NN];             // u = exp(X @ c)
__device__ float    g_r[BB * NN];             // r = u / (A@u)
__device__ float    g_xpart[BB * 128 * FF];   // per-block partial col-sums of X
__device__ float    g_S[BB * FF];             // S = (sum_n X) @ W
__device__ unsigned g_bits[BB * NN * NWRD];   // A != 0 bitmask (4 MB)
__device__ int      g_done[BB];               // per-batch k3 completion counter
// Bit layout (lane-local): word w (0..63): L = w&31, half = w>>5;
//   nibble j' (0..7) of word w covers columns (half*8+j')*128 + L*4 + {0..3}

// ---------------- k0: c = W @ a_i (warp per output); zero pipeline counters -
__global__ void k0_c(const float* __restrict__ W, const float* __restrict__ a)
{
    if (blockIdx.x == 0 && threadIdx.x < BB) g_done[threadIdx.x] = 0;

    const int warp = (blockIdx.x * 1024 + threadIdx.x) >> 5;  // = fi
    const int lane = threadIdx.x & 31;

    float4 w4 = reinterpret_cast<const float4*>(W + warp * FF)[lane];
    float4 a4 = reinterpret_cast<const float4*>(a + FF)[lane];   // a_i
    float s = w4.x * a4.x + w4.y * a4.y + w4.z * a4.z + w4.w * a4.w;
#pragma unroll
    for (int off = 16; off; off >>= 1)
        s += __shfl_xor_sync(0xffffffffu, s, off);
    if (lane == 0) g_c[warp] = s;
}

// ---------------- k1: u = exp(X @ c); per-block partial column-sums of X ----
// grid (128, 8), block 512 (16 warps, 1 row per warp)
__global__ void k1_u_xsum(const float* __restrict__ X)
{
    const int b    = blockIdx.y;
    const int warp = threadIdx.x >> 5;
    const int lane = threadIdx.x & 31;

    __shared__ float sc[FF];
    __shared__ float sx[16][FF];
    if (threadIdx.x < FF) sc[threadIdx.x] = g_c[threadIdx.x];
    __syncthreads();

    const int row = blockIdx.x * 16 + warp;
    float4 x4 = reinterpret_cast<const float4*>(
                    X + ((size_t)b * NN + row) * FF)[lane];
    float4 c4 = reinterpret_cast<const float4*>(sc)[lane];

    float s = x4.x * c4.x + x4.y * c4.y + x4.z * c4.z + x4.w * c4.w;
#pragma unroll
    for (int off = 16; off; off >>= 1)
        s += __shfl_xor_sync(0xffffffffu, s, off);
    if (lane == 0) g_u[(size_t)b * NN + row] = expf(s);

    reinterpret_cast<float4*>(sx[warp])[lane] = x4;
    __syncthreads();
    if (threadIdx.x < FF) {
        float v = 0.f;
#pragma unroll
        for (int w2 = 0; w2 < 16; w2++) v += sx[w2][threadIdx.x];
        g_xpart[((size_t)b * 128 + blockIdx.x) * FF + threadIdx.x] = v;
    }
}

// ---------------- fused k3+k5: software-pipelined via g_done[b] -------------
// Blocks [0, 1032): k3 work, batch-major (129/batch: 128 A-scan + 1 S).
// Blocks [1032, 1544): k5 work (64/batch); spin until g_done[b] == 129.
// Deadlock-free: 512 k5 blocks < 592 resident slots -> k3 always progresses.
__global__ void __launch_bounds__(512) k35_fused(const float* __restrict__ A,
                                                 const float* __restrict__ W,
                                                 float* __restrict__ H,
                                                 const float* __restrict__ biasW)
{
    __shared__ float smem[16 * 512 + 2 * FF];   // union: tab | tab+sS+sbw
    float* tab = smem;                          // [16][512] subset-major

    if (blockIdx.x < K3_BLKS) {
        // ======================= k3 region ==================================
        const int b   = blockIdx.x / 129;
        const int sub = blockIdx.x % 129;

        if (sub == 128) {
            // ---- S path: xs = sum of g_xpart chunks; S = xs @ W ----
            float* part = smem;                 // [4][FF]
            float* xs   = smem + 4 * FF;
            float* dot  = smem + 5 * FF;        // [4][FF]
            const int t = threadIdx.x & 127;
            const int p = threadIdx.x >> 7;     // 0..3
            float v = 0.f;
#pragma unroll 8
            for (int c = 0; c < 32; c++)
                v += g_xpart[((size_t)b * 128 + p * 32 + c) * FF + t];
            part[p * FF + t] = v;
            __syncthreads();
            if (threadIdx.x < FF)
                xs[t] = part[t] + part[FF + t] + part[2 * FF + t] + part[3 * FF + t];
            __syncthreads();
            float s = 0.f;
#pragma unroll 8
            for (int k = 0; k < 32; k++) {
                const int fi = p * 32 + k;
                s += xs[fi] * W[fi * FF + t];
            }
            dot[p * FF + t] = s;
            __syncthreads();
            if (threadIdx.x < FF)
                g_S[b * FF + t] = dot[t] + dot[FF + t] + dot[2 * FF + t] + dot[3 * FF + t];
            __syncthreads();
            if (threadIdx.x == 0) { __threadfence(); atomicAdd(&g_done[b], 1); }
            return;
        }

        const int warp = threadIdx.x >> 5;
        const int lane = threadIdx.x & 31;
        const int row  = sub * 16 + warp;

        const uint4* Ar = reinterpret_cast<const uint4*>(
                              A + ((size_t)(b * NN + row)) * NN);

        // Issue half-0 loads immediately (8 LDG.128 in flight per warp).
        uint4 v[8];
#pragma unroll
        for (int k = 0; k < 8; k++) v[k] = __ldcs(&Ar[k * 32 + lane]);

        {   // u nibble-LUT: tab[v][G] = sum of u over subset v of cols 4G..4G+3
            const int g = threadIdx.x;
            const float4 s = reinterpret_cast<const float4*>(g_u + (size_t)b * NN)[g];
            const float s01 = s.x + s.y;
            const float s23 = s.z + s.w;
            tab[0*512+g]  = 0.f;        tab[1*512+g]  = s.x;        tab[2*512+g]  = s.y;
            tab[3*512+g]  = s01;        tab[4*512+g]  = s.z;        tab[5*512+g]  = s.x + s.z;
            tab[6*512+g]  = s.y + s.z;  tab[7*512+g]  = s01 + s.z;  tab[8*512+g]  = s.w;
            tab[9*512+g]  = s.x + s.w;  tab[10*512+g] = s.y + s.w;  tab[11*512+g] = s01 + s.w;
            tab[12*512+g] = s23;        tab[13*512+g] = s.x + s23;  tab[14*512+g] = s.y + s23;
            tab[15*512+g] = s01 + s23;
        }
        __syncthreads();

        float acc0 = 0.f, acc1 = 0.f;
        unsigned w0 = 0u, w1 = 0u;

#pragma unroll
        for (int k = 0; k < 8; k++) {
            // 1.0f = 0x3F800000 (bit 29 set); 0.0f = 0. Pure integer decode.
            unsigned nib = ((v[k].x >> 29) & 1u) | ((v[k].y >> 28) & 2u)
                         | ((v[k].z >> 27) & 4u) | ((v[k].w >> 26) & 8u);
            w0 |= nib << (4 * k);
            acc0 += tab[nib * 512 + k * 32 + lane];
        }
#pragma unroll
        for (int k = 0; k < 8; k++) v[k] = __ldcs(&Ar[(8 + k) * 32 + lane]);
#pragma unroll
        for (int k = 0; k < 8; k++) {
            unsigned nib = ((v[k].x >> 29) & 1u) | ((v[k].y >> 28) & 2u)
                         | ((v[k].z >> 27) & 4u) | ((v[k].w >> 26) & 8u);
            w1 |= nib << (4 * k);
            acc1 += tab[nib * 512 + (8 + k) * 32 + lane];
        }

        float acc = acc0 + acc1;
#pragma unroll
        for (int off = 16; off; off >>= 1)
            acc += __shfl_xor_sync(0xffffffffu, acc, off);   // w = (A@u)[row]

        unsigned* br = g_bits + ((size_t)(b * NN + row)) * NWRD;
        br[lane]      = w0;
        br[32 + lane] = w1;
        if (lane == 0) {
            float u_row = g_u[(size_t)b * NN + row];
            g_r[(size_t)b * NN + row] = (acc != 0.f) ? __fdividef(u_row, acc) : 0.f;
        }
        __syncthreads();
        if (threadIdx.x == 0) { __threadfence(); atomicAdd(&g_done[b], 1); }
        return;
    }

    // =========================== k5 region ==================================
    const int t5  = blockIdx.x - K3_BLKS;
    const int b   = t5 >> 6;            // / 64
    const int blk = t5 & 63;

    if (threadIdx.x == 0) {             // wait for batch b's k3 to finish
        while (*(volatile int*)&g_done[b] < 129) __nanosleep(128);
    }
    __syncthreads();
    __threadfence();                    // acquire: see k3's stores

    float* sS  = smem + 16 * 512;
    float* sbw = sS + FF;

    if (threadIdx.x < FF) {
        sS[threadIdx.x]  = g_S[b * FF + threadIdx.x];
        sbw[threadIdx.x] = biasW[threadIdx.x];
    }
    {   // build LUT from g_r (coalesced float4)
        const int g = threadIdx.x;
        const float4 s = reinterpret_cast<const float4*>(g_r + (size_t)b * NN)[g];
        const float s01 = s.x + s.y;
        const float s23 = s.z + s.w;
        tab[0*512+g]  = 0.f;        tab[1*512+g]  = s.x;        tab[2*512+g]  = s.y;
        tab[3*512+g]  = s01;        tab[4*512+g]  = s.z;        tab[5*512+g]  = s.x + s.z;
        tab[6*512+g]  = s.y + s.z;  tab[7*512+g]  = s01 + s.z;  tab[8*512+g]  = s.w;
        tab[9*512+g]  = s.x + s.w;  tab[10*512+g] = s.y + s.w;  tab[11*512+g] = s01 + s.w;
        tab[12*512+g] = s23;        tab[13*512+g] = s.x + s23;  tab[14*512+g] = s.y + s23;
        tab[15*512+g] = s01 + s23;
    }
    __syncthreads();

    const int warp = threadIdx.x >> 5;
    const int lane = threadIdx.x & 31;
    const int row0 = blk * 32 + warp * 2;     // 2 rows per warp

    const unsigned* bb = g_bits + ((size_t)(b * NN + row0)) * NWRD;
    const unsigned wA0 = bb[lane];
    const unsigned wA1 = bb[32 + lane];
    const unsigned wB0 = bb[NWRD + lane];
    const unsigned wB1 = bb[NWRD + 32 + lane];

    float aA0 = 0.f, aA1 = 0.f, aB0 = 0.f, aB1 = 0.f;
#pragma unroll
    for (int j = 0; j < 8; j++) {
        const int base0 = j * 32 + lane;
        const int base1 = (8 + j) * 32 + lane;
        aA0 += tab[((wA0 >> (4 * j)) & 15u) * 512 + base0];
        aA1 += tab[((wA1 >> (4 * j)) & 15u) * 512 + base1];
        aB0 += tab[((wB0 >> (4 * j)) & 15u) * 512 + base0];
        aB1 += tab[((wB1 >> (4 * j)) & 15u) * 512 + base1];
    }
    float accA = aA0 + aA1;
    float accB = aB0 + aB1;
#pragma unroll
    for (int off = 16; off; off >>= 1) {
        accA += __shfl_xor_sync(0xffffffffu, accA, off);   // q[row0]
        accB += __shfl_xor_sync(0xffffffffu, accB, off);   // q[row0+1]
    }

    const float4 s4 = reinterpret_cast<const float4*>(sS)[lane];
    const float4 w4 = reinterpret_cast<const float4*>(sbw)[lane];
    float4 oA, oB;
    oA.x = accA * s4.x + w4.x;  oA.y = accA * s4.y + w4.y;
    oA.z = accA * s4.z + w4.z;  oA.w = accA * s4.w + w4.w;
    oB.x = accB * s4.x + w4.x;  oB.y = accB * s4.y + w4.y;
    oB.z = accB * s4.z + w4.z;  oB.w = accB * s4.w + w4.w;
    reinterpret_cast<float4*>(H + ((size_t)(b * NN + row0)) * FF)[lane]     = oA;
    reinterpret_cast<float4*>(H + ((size_t)(b * NN + row0 + 1)) * FF)[lane] = oB;
}

// ---------------- launch -----------------------------------------------------
extern "C" void kernel_launch(void* const* d_in, const int* in_sizes, int n_in,
                              void* d_out, int out_size)
{
    const float* X     = (const float*)d_in[0];
    const float* A     = (const float*)d_in[1];
    const float* W     = (const float*)d_in[2];
    const float* a     = (const float*)d_in[3];
    // d_in[4] = bias_a: cancels analytically (rank-1 den), unused.
    const float* biasW = (const float*)d_in[5];
    float* H = (float*)d_out;

    k0_c     <<<4, 1024>>>(W, a);          // also zeroes g_done
    k1_u_xsum<<<dim3(128, BB), 512>>>(X);
    k35_fused<<<ALL_BLKS, 512>>>(A, W, H, biasW);
}